// round 1
// baseline (speedup 1.0000x reference)
#include <cuda_runtime.h>
#include <math.h>

#define D_MODEL 1024
#define D_KEY   128
#define N_SUB   256
#define TOPK    8
#define MAXNT   8192

// -------- scratch (device globals: no allocation allowed) --------
__device__ float g_q[MAXNT * 2 * D_KEY];       // [NT, 256]
__device__ float g_scores[MAXNT * 2 * N_SUB];  // [NT, 512] : [0,256)=a, [256,512)=b
__device__ float g_wts[MAXNT * TOPK];
__device__ int   g_idx[MAXNT * TOPK];

// ---------------- generic fp32 GEMM: C[M,N] = A[M,K] * B[N,K]^T ----------------
// A row-major with leading dim lda, column offset aoff.
// B row-major with leading dim ldb (K contiguous).
// C row-major with leading dim ldc, column offset coff.
#define BM 128
#define BN 64
#define BK 16

__global__ __launch_bounds__(256) void sgemm_tn(
    const float* __restrict__ A, int lda, int aoff,
    const float* __restrict__ B, int ldb,
    float* __restrict__ C, int ldc, int coff,
    int K)
{
    __shared__ float As[BK][BM + 4];  // transposed: As[k][m], padded for banks/alignment
    __shared__ float Bs[BK][BN + 4];  // Bs[k][n]

    const int m0 = blockIdx.x * BM;
    const int n0 = blockIdx.y * BN;
    const int tid = threadIdx.x;
    const int tx = tid & 15;   // N direction (TN=4)
    const int ty = tid >> 4;   // M direction (TM=8)

    const float* Ab = A + (size_t)m0 * lda + aoff;
    const float* Bb = B + (size_t)n0 * ldb;

    float acc[8][4];
    #pragma unroll
    for (int i = 0; i < 8; i++)
        #pragma unroll
        for (int j = 0; j < 4; j++) acc[i][j] = 0.f;

    for (int k0 = 0; k0 < K; k0 += BK) {
        // load A tile: 128 rows x 16 k = 512 float4, 2 per thread
        #pragma unroll
        for (int u = 0; u < 2; u++) {
            int id = tid + u * 256;       // 0..511
            int r  = id >> 2;             // 0..127
            int c4 = id & 3;              // 0..3
            float4 v = *(const float4*)(Ab + (size_t)r * lda + k0 + c4 * 4);
            As[c4 * 4 + 0][r] = v.x;
            As[c4 * 4 + 1][r] = v.y;
            As[c4 * 4 + 2][r] = v.z;
            As[c4 * 4 + 3][r] = v.w;
        }
        // load B tile: 64 rows x 16 k = 256 float4, 1 per thread
        {
            int r  = tid >> 2;            // 0..63
            int c4 = tid & 3;             // 0..3
            float4 v = *(const float4*)(Bb + (size_t)r * ldb + k0 + c4 * 4);
            Bs[c4 * 4 + 0][r] = v.x;
            Bs[c4 * 4 + 1][r] = v.y;
            Bs[c4 * 4 + 2][r] = v.z;
            Bs[c4 * 4 + 3][r] = v.w;
        }
        __syncthreads();

        #pragma unroll
        for (int k = 0; k < BK; k++) {
            float4 a0 = *(const float4*)&As[k][ty * 8];
            float4 a1 = *(const float4*)&As[k][ty * 8 + 4];
            float4 b  = *(const float4*)&Bs[k][tx * 4];
            float av[8] = {a0.x, a0.y, a0.z, a0.w, a1.x, a1.y, a1.z, a1.w};
            float bv[4] = {b.x, b.y, b.z, b.w};
            #pragma unroll
            for (int i = 0; i < 8; i++)
                #pragma unroll
                for (int j = 0; j < 4; j++)
                    acc[i][j] = fmaf(av[i], bv[j], acc[i][j]);
        }
        __syncthreads();
    }

    // store (float4 per output row chunk)
    #pragma unroll
    for (int i = 0; i < 8; i++) {
        float4 o = make_float4(acc[i][0], acc[i][1], acc[i][2], acc[i][3]);
        *(float4*)(C + (size_t)(m0 + ty * 8 + i) * ldc + coff + n0 + tx * 4) = o;
    }
}

// ---------------- top-k kernel: one block per token ----------------
__global__ __launch_bounds__(256) void topk_kernel(
    const float* __restrict__ scores,
    float* __restrict__ wts, int* __restrict__ idxs)
{
    const int t = blockIdx.x;
    const int tid = threadIdx.x;
    const int lane = tid & 31, wid = tid >> 5;

    __shared__ float sv[2 * N_SUB];
    __shared__ float wv[8];  __shared__ int wi[8];
    __shared__ float topv[2][TOPK]; __shared__ int topi[2][TOPK];
    __shared__ float cv[64]; __shared__ int ci[64];

    const float* srow = scores + (size_t)t * (2 * N_SUB);
    sv[tid]       = srow[tid];
    sv[tid + 256] = srow[tid + 256];
    __syncthreads();

    // top-8 of each 256-score half via iterated argmax
    for (int h = 0; h < 2; h++) {
        float* s = sv + h * 256;
        for (int it = 0; it < TOPK; it++) {
            float v = s[tid]; int i = tid;
            #pragma unroll
            for (int off = 16; off; off >>= 1) {
                float ov = __shfl_down_sync(0xffffffffu, v, off);
                int   oi = __shfl_down_sync(0xffffffffu, i, off);
                if (ov > v || (ov == v && oi < i)) { v = ov; i = oi; }
            }
            if (lane == 0) { wv[wid] = v; wi[wid] = i; }
            __syncthreads();
            if (tid == 0) {
                float bv = wv[0]; int bi = wi[0];
                #pragma unroll
                for (int w = 1; w < 8; w++)
                    if (wv[w] > bv || (wv[w] == bv && wi[w] < bi)) { bv = wv[w]; bi = wi[w]; }
                topv[h][it] = bv; topi[h][it] = bi;
                s[bi] = -INFINITY;
            }
            __syncthreads();
        }
    }

    // 64 cartesian candidates
    if (tid < 64) {
        int ka = tid >> 3, kb = tid & 7;
        cv[tid] = topv[0][ka] + topv[1][kb];
        ci[tid] = topi[0][ka] * N_SUB + topi[1][kb];
    }
    __syncthreads();

    // warp 0: top-8 of 64, then softmax + output
    if (tid < 32) {
        float fvv[TOPK]; int fii[TOPK];
        for (int it = 0; it < TOPK; it++) {
            float v0 = cv[tid], v1 = cv[tid + 32];
            float v; int i;
            if (v1 > v0) { v = v1; i = tid + 32; } else { v = v0; i = tid; }
            #pragma unroll
            for (int off = 16; off; off >>= 1) {
                float ov = __shfl_down_sync(0xffffffffu, v, off);
                int   oi = __shfl_down_sync(0xffffffffu, i, off);
                if (ov > v || (ov == v && oi < i)) { v = ov; i = oi; }
            }
            v = __shfl_sync(0xffffffffu, v, 0);
            i = __shfl_sync(0xffffffffu, i, 0);
            fvv[it] = v; fii[it] = ci[i];
            if (tid == (i & 31)) cv[i] = -INFINITY;
            __syncwarp();
        }
        if (tid == 0) {
            float m = fvv[0];
            #pragma unroll
            for (int k = 1; k < TOPK; k++) m = fmaxf(m, fvv[k]);
            float e[TOPK], ssum = 0.f;
            #pragma unroll
            for (int k = 0; k < TOPK; k++) { e[k] = expf(fvv[k] - m); ssum += e[k]; }
            float inv = 1.f / ssum;
            #pragma unroll
            for (int k = 0; k < TOPK; k++) {
                wts[(size_t)t * TOPK + k]  = e[k] * inv;
                idxs[(size_t)t * TOPK + k] = fii[k];
            }
        }
    }
}

// ---------------- gather + gate + residual: one block per token ----------------
__global__ __launch_bounds__(256) void gather_kernel(
    const float* __restrict__ x, const float* __restrict__ values,
    const float* __restrict__ gate_w, const float* __restrict__ gate_b,
    const float* __restrict__ wts, const int* __restrict__ idxs,
    float* __restrict__ out)
{
    const int t = blockIdx.x;
    const int tid = threadIdx.x;       // 256 threads, one float4 column each
    const int lane = tid & 31, wid = tid >> 5;

    const float4* xr = (const float4*)(x + (size_t)t * D_MODEL);
    const float4* gw = (const float4*)gate_w;

    float4 xv = xr[tid];
    float4 gv = gw[tid];
    float p = xv.x * gv.x + xv.y * gv.y + xv.z * gv.z + xv.w * gv.w;
    #pragma unroll
    for (int off = 16; off; off >>= 1) p += __shfl_down_sync(0xffffffffu, p, off);

    __shared__ float red[8];
    __shared__ float sw[TOPK];
    __shared__ int   sid[TOPK];
    __shared__ float sg;
    if (lane == 0) red[wid] = p;
    if (tid >= 32 && tid < 32 + TOPK) {
        sw[tid - 32]  = wts[(size_t)t * TOPK + (tid - 32)];
        sid[tid - 32] = idxs[(size_t)t * TOPK + (tid - 32)];
    }
    __syncthreads();
    if (tid == 0) {
        float s = red[0];
        #pragma unroll
        for (int w = 1; w < 8; w++) s += red[w];
        sg = 1.f / (1.f + expf(-(s + gate_b[0])));
    }
    __syncthreads();
    const float g = sg;

    float4 acc = make_float4(0.f, 0.f, 0.f, 0.f);
    #pragma unroll
    for (int k = 0; k < TOPK; k++) {
        const float4* vr = (const float4*)(values + (size_t)sid[k] * D_MODEL);
        float4 vv = __ldg(vr + tid);
        float w = sw[k];
        acc.x += w * vv.x; acc.y += w * vv.y; acc.z += w * vv.z; acc.w += w * vv.w;
    }
    float4 o;
    o.x = xv.x + g * acc.x;
    o.y = xv.y + g * acc.y;
    o.z = xv.z + g * acc.z;
    o.w = xv.w + g * acc.w;
    ((float4*)(out + (size_t)t * D_MODEL))[tid] = o;
}

// ---------------- launch ----------------
extern "C" void kernel_launch(void* const* d_in, const int* in_sizes, int n_in,
                              void* d_out, int out_size)
{
    const float* x      = (const float*)d_in[0];
    const float* keys_a = (const float*)d_in[1];
    const float* keys_b = (const float*)d_in[2];
    const float* values = (const float*)d_in[3];
    const float* Wq     = (const float*)d_in[4];
    const float* gate_w = (const float*)d_in[5];
    const float* gate_b = (const float*)d_in[6];
    float* out = (float*)d_out;

    const int NT = in_sizes[0] / D_MODEL;   // 8192

    float* qbuf; float* sbuf; float* wbuf; int* ibuf;
    cudaGetSymbolAddress((void**)&qbuf, g_q);
    cudaGetSymbolAddress((void**)&sbuf, g_scores);
    cudaGetSymbolAddress((void**)&wbuf, g_wts);
    cudaGetSymbolAddress((void**)&ibuf, g_idx);

    // 1) q = x @ Wq^T   [NT,1024] x [256,1024]^T -> [NT,256]
    {
        dim3 grid(NT / BM, (2 * D_KEY) / BN);
        sgemm_tn<<<grid, 256>>>(x, D_MODEL, 0, Wq, D_MODEL, qbuf, 2 * D_KEY, 0, D_MODEL);
    }
    // 2) scores_a = qa @ keys_a^T ; scores_b = qb @ keys_b^T  -> [NT,512]
    {
        dim3 grid(NT / BM, N_SUB / BN);
        sgemm_tn<<<grid, 256>>>(qbuf, 2 * D_KEY, 0,     keys_a, D_KEY, sbuf, 2 * N_SUB, 0,     D_KEY);
        sgemm_tn<<<grid, 256>>>(qbuf, 2 * D_KEY, D_KEY, keys_b, D_KEY, sbuf, 2 * N_SUB, N_SUB, D_KEY);
    }
    // 3) top-k + softmax
    topk_kernel<<<NT, 256>>>(sbuf, wbuf, ibuf);
    // 4) gather + gate + residual
    gather_kernel<<<NT, 256>>>(x, values, gate_w, gate_b, wbuf, ibuf, out);
}

// round 2
// speedup vs baseline: 1.1289x; 1.1289x over previous
#include <cuda_runtime.h>
#include <math.h>

#define D_MODEL 1024
#define D_KEY   128
#define N_SUB   256
#define TOPK    8
#define MAXNT   8192

__device__ float g_q[MAXNT * 2 * D_KEY];       // [NT, 256]
__device__ float g_scores[MAXNT * 2 * N_SUB];  // [NT, 512]
__device__ float g_wts[MAXNT * TOPK];
__device__ int   g_idx[MAXNT * TOPK];

typedef unsigned long long ull;

__device__ __forceinline__ ull fma2(ull a, ull b, ull c) {
    ull d;
    asm("fma.rn.f32x2 %0, %1, %2, %3;" : "=l"(d) : "l"(a), "l"(b), "l"(c));
    return d;
}

// ================= f32x2 GEMM: C[M,N] = A[M,K] * B[N,K]^T =================
// BM=BN=128, BK=16, 256 threads, 8x8 per thread via packed f32x2 FMA.
// A tile stored DUPLICATED in smem so LDS yields (a,a) pairs directly.
// blockIdx.z selects (A column offset, B matrix, C column offset) so the two
// score GEMMs run as one launch.
#define BM 128
#define BN 128
#define BK 16
#define AS_LD (2*BM + 4)   // 260 floats per k-row (16B-aligned rows)
#define BS_LD (BN + 4)     // 132

__global__ __launch_bounds__(256) void sgemm_f32x2(
    const float* __restrict__ A, int lda, int aoff_step,
    const float* __restrict__ B0, const float* __restrict__ B1, int ldb,
    float* __restrict__ C, int ldc, int coff_step,
    int K)
{
    __shared__ float As2[BK][AS_LD];
    __shared__ float Bs[BK][BS_LD];

    const int z    = blockIdx.z;
    const int aoff = z * aoff_step;
    const int coff = z * coff_step;
    const float* __restrict__ B = z ? B1 : B0;

    const int m0 = blockIdx.x * BM;
    const int n0 = blockIdx.y * BN;
    const int tid = threadIdx.x;
    const int tx = tid & 15;   // N: 16 x 8 = 128
    const int ty = tid >> 4;   // M: 16 x 8 = 128

    const float* Ab = A + (size_t)m0 * lda + aoff;
    const float* Bb = B + (size_t)n0 * ldb;

    ull acc[8][4];
    #pragma unroll
    for (int i = 0; i < 8; i++)
        #pragma unroll
        for (int j = 0; j < 4; j++) acc[i][j] = 0ull;

    for (int k0 = 0; k0 < K; k0 += BK) {
        // A tile: 128 rows x 16 k = 512 float4, 2 per thread, duplicated store
        #pragma unroll
        for (int u = 0; u < 2; u++) {
            int id = tid + u * 256;
            int r  = id >> 2;
            int c4 = id & 3;
            float4 v = *(const float4*)(Ab + (size_t)r * lda + k0 + c4 * 4);
            As2[c4*4 + 0][2*r] = v.x;  As2[c4*4 + 0][2*r + 1] = v.x;
            As2[c4*4 + 1][2*r] = v.y;  As2[c4*4 + 1][2*r + 1] = v.y;
            As2[c4*4 + 2][2*r] = v.z;  As2[c4*4 + 2][2*r + 1] = v.z;
            As2[c4*4 + 3][2*r] = v.w;  As2[c4*4 + 3][2*r + 1] = v.w;
        }
        // B tile: 128 rows x 16 k = 512 float4, 2 per thread
        #pragma unroll
        for (int u = 0; u < 2; u++) {
            int id = tid + u * 256;
            int r  = id >> 2;
            int c4 = id & 3;
            float4 v = *(const float4*)(Bb + (size_t)r * ldb + k0 + c4 * 4);
            Bs[c4*4 + 0][r] = v.x;
            Bs[c4*4 + 1][r] = v.y;
            Bs[c4*4 + 2][r] = v.z;
            Bs[c4*4 + 3][r] = v.w;
        }
        __syncthreads();

        #pragma unroll
        for (int k = 0; k < BK; k++) {
            ulonglong2 a01 = *(const ulonglong2*)&As2[k][ty*16 + 0];
            ulonglong2 a23 = *(const ulonglong2*)&As2[k][ty*16 + 4];
            ulonglong2 a45 = *(const ulonglong2*)&As2[k][ty*16 + 8];
            ulonglong2 a67 = *(const ulonglong2*)&As2[k][ty*16 + 12];
            ulonglong2 b01 = *(const ulonglong2*)&Bs[k][tx*8 + 0];
            ulonglong2 b23 = *(const ulonglong2*)&Bs[k][tx*8 + 4];
            ull av[8] = {a01.x, a01.y, a23.x, a23.y, a45.x, a45.y, a67.x, a67.y};
            ull bv[4] = {b01.x, b01.y, b23.x, b23.y};
            #pragma unroll
            for (int i = 0; i < 8; i++)
                #pragma unroll
                for (int j = 0; j < 4; j++)
                    acc[i][j] = fma2(av[i], bv[j], acc[i][j]);
        }
        __syncthreads();
    }

    #pragma unroll
    for (int i = 0; i < 8; i++) {
        float* crow = C + (size_t)(m0 + ty*8 + i) * ldc + coff + n0 + tx*8;
        ulonglong2 s0; s0.x = acc[i][0]; s0.y = acc[i][1];
        ulonglong2 s1; s1.x = acc[i][2]; s1.y = acc[i][3];
        *(ulonglong2*)(crow)     = s0;
        *(ulonglong2*)(crow + 4) = s1;
    }
}

// ================= warp-per-token top-k (registers + shuffles only) =================
__global__ __launch_bounds__(256) void topk_warp(
    const float* __restrict__ scores,
    float* __restrict__ wts, int* __restrict__ idxs, int NT)
{
    const int lane = threadIdx.x & 31;
    const int t = blockIdx.x * 8 + (threadIdx.x >> 5);
    if (t >= NT) return;
    const float* row = scores + (size_t)t * (2 * N_SUB);

    float va[8], vb[8];
    {
        float4 p0 = *(const float4*)(row + lane*8);
        float4 p1 = *(const float4*)(row + lane*8 + 4);
        va[0]=p0.x; va[1]=p0.y; va[2]=p0.z; va[3]=p0.w;
        va[4]=p1.x; va[5]=p1.y; va[6]=p1.z; va[7]=p1.w;
        float4 q0 = *(const float4*)(row + 256 + lane*8);
        float4 q1 = *(const float4*)(row + 256 + lane*8 + 4);
        vb[0]=q0.x; vb[1]=q0.y; vb[2]=q0.z; vb[3]=q0.w;
        vb[4]=q1.x; vb[5]=q1.y; vb[6]=q1.z; vb[7]=q1.w;
    }

    float ta_v = 0.f, tb_v = 0.f;   // lane `it` holds it-th winner
    int   ta_i = 0,   tb_i = 0;

    // ---- half A: 8 iterated argmax over 256 values ----
    #pragma unroll
    for (int it = 0; it < TOPK; it++) {
        float bv = va[0]; int bs = 0;
        #pragma unroll
        for (int s = 1; s < 8; s++) if (va[s] > bv) { bv = va[s]; bs = s; }
        int bi = lane*8 + bs;
        #pragma unroll
        for (int off = 16; off; off >>= 1) {
            float ov = __shfl_down_sync(0xffffffffu, bv, off);
            int   oi = __shfl_down_sync(0xffffffffu, bi, off);
            if (ov > bv || (ov == bv && oi < bi)) { bv = ov; bi = oi; }
        }
        bv = __shfl_sync(0xffffffffu, bv, 0);
        bi = __shfl_sync(0xffffffffu, bi, 0);
        if (lane == it) { ta_v = bv; ta_i = bi; }
        if ((bi >> 3) == lane) {
            int s0 = bi & 7;
            #pragma unroll
            for (int s = 0; s < 8; s++) if (s == s0) va[s] = -INFINITY;
        }
    }
    // ---- half B ----
    #pragma unroll
    for (int it = 0; it < TOPK; it++) {
        float bv = vb[0]; int bs = 0;
        #pragma unroll
        for (int s = 1; s < 8; s++) if (vb[s] > bv) { bv = vb[s]; bs = s; }
        int bi = lane*8 + bs;
        #pragma unroll
        for (int off = 16; off; off >>= 1) {
            float ov = __shfl_down_sync(0xffffffffu, bv, off);
            int   oi = __shfl_down_sync(0xffffffffu, bi, off);
            if (ov > bv || (ov == bv && oi < bi)) { bv = ov; bi = oi; }
        }
        bv = __shfl_sync(0xffffffffu, bv, 0);
        bi = __shfl_sync(0xffffffffu, bi, 0);
        if (lane == it) { tb_v = bv; tb_i = bi; }
        if ((bi >> 3) == lane) {
            int s0 = bi & 7;
            #pragma unroll
            for (int s = 0; s < 8; s++) if (s == s0) vb[s] = -INFINITY;
        }
    }

    // ---- 64 cartesian combos: lane holds positions lane and lane+32 ----
    float a0v = __shfl_sync(0xffffffffu, ta_v, lane >> 3);
    float a1v = __shfl_sync(0xffffffffu, ta_v, (lane >> 3) + 4);
    int   a0i = __shfl_sync(0xffffffffu, ta_i, lane >> 3);
    int   a1i = __shfl_sync(0xffffffffu, ta_i, (lane >> 3) + 4);
    float bbv = __shfl_sync(0xffffffffu, tb_v, lane & 7);
    int   bbi = __shfl_sync(0xffffffffu, tb_i, lane & 7);

    float cv0 = a0v + bbv;  int ci0 = a0i * N_SUB + bbi;
    float cv1 = a1v + bbv;  int ci1 = a1i * N_SUB + bbi;

    float fv = 0.f; int fidx = 0;
    #pragma unroll
    for (int it = 0; it < TOPK; it++) {
        float bv; int bp, bi;
        if (cv1 > cv0) { bv = cv1; bp = lane + 32; bi = ci1; }
        else           { bv = cv0; bp = lane;      bi = ci0; }
        #pragma unroll
        for (int off = 16; off; off >>= 1) {
            float ov = __shfl_down_sync(0xffffffffu, bv, off);
            int   op = __shfl_down_sync(0xffffffffu, bp, off);
            int   oi = __shfl_down_sync(0xffffffffu, bi, off);
            if (ov > bv || (ov == bv && op < bp)) { bv = ov; bp = op; bi = oi; }
        }
        bv = __shfl_sync(0xffffffffu, bv, 0);
        bp = __shfl_sync(0xffffffffu, bp, 0);
        bi = __shfl_sync(0xffffffffu, bi, 0);
        if (lane == it) { fv = bv; fidx = bi; }
        if (bp == lane)      cv0 = -INFINITY;
        if (bp == lane + 32) cv1 = -INFINITY;
    }

    // ---- softmax over the 8 winners (held by lanes 0..7) ----
    float fmaxv = __shfl_sync(0xffffffffu, fv, 0);   // first winner is the max
    float e = (lane < TOPK) ? __expf(fv - fmaxv) : 0.f;
    // recompute with expf for accuracy
    e = (lane < TOPK) ? expf(fv - fmaxv) : 0.f;
    float ssum = e;
    #pragma unroll
    for (int off = 16; off; off >>= 1) ssum += __shfl_xor_sync(0xffffffffu, ssum, off);
    if (lane < TOPK) {
        wts[(size_t)t * TOPK + lane]  = e / ssum;
        idxs[(size_t)t * TOPK + lane] = fidx;
    }
}

// ================= gather + gate + residual =================
__global__ __launch_bounds__(256) void gather_kernel(
    const float* __restrict__ x, const float* __restrict__ values,
    const float* __restrict__ gate_w, const float* __restrict__ gate_b,
    const float* __restrict__ wts, const int* __restrict__ idxs,
    float* __restrict__ out)
{
    const int t = blockIdx.x;
    const int tid = threadIdx.x;
    const int lane = tid & 31, wid = tid >> 5;

    const float4* xr = (const float4*)(x + (size_t)t * D_MODEL);
    const float4* gw = (const float4*)gate_w;

    float4 xv = xr[tid];
    float4 gv = gw[tid];
    float p = xv.x * gv.x + xv.y * gv.y + xv.z * gv.z + xv.w * gv.w;
    #pragma unroll
    for (int off = 16; off; off >>= 1) p += __shfl_down_sync(0xffffffffu, p, off);

    __shared__ float red[8];
    __shared__ float sw[TOPK];
    __shared__ int   sid[TOPK];
    __shared__ float sg;
    if (lane == 0) red[wid] = p;
    if (tid >= 32 && tid < 32 + TOPK) {
        sw[tid - 32]  = wts[(size_t)t * TOPK + (tid - 32)];
        sid[tid - 32] = idxs[(size_t)t * TOPK + (tid - 32)];
    }
    __syncthreads();
    if (tid == 0) {
        float s = red[0];
        #pragma unroll
        for (int w = 1; w < 8; w++) s += red[w];
        sg = 1.f / (1.f + expf(-(s + gate_b[0])));
    }
    __syncthreads();
    const float g = sg;

    float4 acc = make_float4(0.f, 0.f, 0.f, 0.f);
    #pragma unroll
    for (int k = 0; k < TOPK; k++) {
        const float4* vr = (const float4*)(values + (size_t)sid[k] * D_MODEL);
        float4 vv = __ldg(vr + tid);
        float w = sw[k];
        acc.x += w * vv.x; acc.y += w * vv.y; acc.z += w * vv.z; acc.w += w * vv.w;
    }
    float4 o;
    o.x = xv.x + g * acc.x;
    o.y = xv.y + g * acc.y;
    o.z = xv.z + g * acc.z;
    o.w = xv.w + g * acc.w;
    ((float4*)(out + (size_t)t * D_MODEL))[tid] = o;
}

// ================= launch =================
extern "C" void kernel_launch(void* const* d_in, const int* in_sizes, int n_in,
                              void* d_out, int out_size)
{
    const float* x      = (const float*)d_in[0];
    const float* keys_a = (const float*)d_in[1];
    const float* keys_b = (const float*)d_in[2];
    const float* values = (const float*)d_in[3];
    const float* Wq     = (const float*)d_in[4];
    const float* gate_w = (const float*)d_in[5];
    const float* gate_b = (const float*)d_in[6];
    float* out = (float*)d_out;

    const int NT = in_sizes[0] / D_MODEL;   // 8192

    float* qbuf; float* sbuf; float* wbuf; int* ibuf;
    cudaGetSymbolAddress((void**)&qbuf, g_q);
    cudaGetSymbolAddress((void**)&sbuf, g_scores);
    cudaGetSymbolAddress((void**)&wbuf, g_wts);
    cudaGetSymbolAddress((void**)&ibuf, g_idx);

    // 1) q = x @ Wq^T : [NT,1024] x [256,1024]^T -> [NT,256]
    {
        dim3 grid(NT / BM, (2 * D_KEY) / BN, 1);
        sgemm_f32x2<<<grid, 256>>>(x, D_MODEL, 0, Wq, Wq, D_MODEL,
                                   qbuf, 2 * D_KEY, 0, D_MODEL);
    }
    // 2) scores (both halves in one launch via grid.z)
    {
        dim3 grid(NT / BM, N_SUB / BN, 2);
        sgemm_f32x2<<<grid, 256>>>(qbuf, 2 * D_KEY, D_KEY, keys_a, keys_b, D_KEY,
                                   sbuf, 2 * N_SUB, N_SUB, D_KEY);
    }
    // 3) top-k + softmax (warp per token)
    topk_warp<<<(NT + 7) / 8, 256>>>(sbuf, wbuf, ibuf, NT);
    // 4) gather + gate + residual
    gather_kernel<<<NT, 256>>>(x, values, gate_w, gate_b, wbuf, ibuf, out);
}

// round 4
// speedup vs baseline: 2.7155x; 2.4053x over previous
#include <cuda_runtime.h>
#include <cuda_bf16.h>
#include <math.h>

#define D_MODEL 1024
#define D_KEY   128
#define N_SUB   256
#define TOPK    8
#define MAXNT   8192

// -------- scratch (device globals) --------
__device__ __align__(128) __nv_bfloat16 g_xb [MAXNT * D_MODEL];
__device__ __align__(128) __nv_bfloat16 g_wqb[2 * D_KEY * D_MODEL];
__device__ __align__(128) __nv_bfloat16 g_kb [2 * N_SUB * D_KEY];
__device__ __align__(128) __nv_bfloat16 g_qb [MAXNT * 2 * D_KEY];
__device__ __align__(128) float g_scores[MAXNT * 2 * N_SUB];
__device__ float g_wts[MAXNT * TOPK];
__device__ int   g_idx[MAXNT * TOPK];

// ================= base-PTX helpers (sm_80-level: OK at compute_103) =================
__device__ __forceinline__ unsigned smem_u32(const void* p) {
    unsigned a;
    asm("{ .reg .u64 t; cvta.to.shared.u64 t, %1; cvt.u32.u64 %0, t; }" : "=r"(a) : "l"(p));
    return a;
}
__device__ __forceinline__ void cpa16(unsigned d, const void* s) {
    asm volatile("cp.async.cg.shared.global [%0], [%1], 16;" :: "r"(d), "l"(s));
}
__device__ __forceinline__ void cpcommit() { asm volatile("cp.async.commit_group;" ::: "memory"); }
template<int N> __device__ __forceinline__ void cpwait() {
    asm volatile("cp.async.wait_group %0;" :: "n"(N) : "memory");
}
__device__ __forceinline__ void ldsm4(unsigned addr, unsigned& r0, unsigned& r1,
                                      unsigned& r2, unsigned& r3) {
    asm volatile("ldmatrix.sync.aligned.m8n8.x4.shared.b16 {%0,%1,%2,%3}, [%4];"
                 : "=r"(r0), "=r"(r1), "=r"(r2), "=r"(r3) : "r"(addr));
}
__device__ __forceinline__ void mma16816(float* c, const unsigned* a, const unsigned* b) {
    asm volatile("mma.sync.aligned.m16n8k16.row.col.f32.bf16.bf16.f32 "
                 "{%0,%1,%2,%3}, {%4,%5,%6,%7}, {%8,%9}, {%0,%1,%2,%3};"
                 : "+f"(c[0]), "+f"(c[1]), "+f"(c[2]), "+f"(c[3])
                 : "r"(a[0]), "r"(a[1]), "r"(a[2]), "r"(a[3]), "r"(b[0]), "r"(b[1]));
}
__device__ __forceinline__ unsigned pk_bf16x2(float a, float b) {
    __nv_bfloat162 h = __floats2bfloat162_rn(a, b);
    return *(unsigned*)&h;
}

// ================= convert fp32 -> bf16 (x, Wq, keys) =================
__global__ __launch_bounds__(256) void convert_kernel(
    const float4* __restrict__ x, const float4* __restrict__ wq,
    const float4* __restrict__ ka, const float4* __restrict__ kb,
    uint2* __restrict__ xb, uint2* __restrict__ wqb, uint2* __restrict__ kbb,
    int X4)
{
    const int W4 = (2 * D_KEY * D_MODEL) / 4;
    const int K4 = (N_SUB * D_KEY) / 4;
    int i = blockIdx.x * blockDim.x + threadIdx.x;
    float4 v; uint2 o;
    if (i < X4) {
        v = x[i];
        o.x = pk_bf16x2(v.x, v.y); o.y = pk_bf16x2(v.z, v.w);
        xb[i] = o;
    } else if (i < X4 + W4) {
        int j = i - X4; v = wq[j];
        o.x = pk_bf16x2(v.x, v.y); o.y = pk_bf16x2(v.z, v.w);
        wqb[j] = o;
    } else if (i < X4 + W4 + K4) {
        int j = i - X4 - W4; v = ka[j];
        o.x = pk_bf16x2(v.x, v.y); o.y = pk_bf16x2(v.z, v.w);
        kbb[j] = o;
    } else if (i < X4 + W4 + 2 * K4) {
        int j = i - X4 - W4 - K4; v = kb[j];
        o.x = pk_bf16x2(v.x, v.y); o.y = pk_bf16x2(v.z, v.w);
        kbb[K4 + j] = o;
    }
}

// ================= HMMA GEMM: C[M, coff+N] = A[M, aoff+K] * Bz[N, K]^T =================
// Block tile 128x128, BK=32, 8 warps (2m x 4n), warp tile 64x32 via mma.m16n8k16.
// 3-stage cp.async pipeline. Smem rows 64B, XOR swizzle: chunk ^= (row>>1)&3.
template<bool OUTBF16>
__global__ __launch_bounds__(256) void hmma_gemm(
    const __nv_bfloat16* __restrict__ A, int lda, int aoff_step,
    const __nv_bfloat16* __restrict__ B0, const __nv_bfloat16* __restrict__ B1, int ldb,
    void* __restrict__ Cv, int ldc, int coff_step, int K)
{
    __shared__ __align__(128) char smem[3 * 16384];   // per stage: A 8KB + B 8KB
    const unsigned sbase = smem_u32(smem);

    const int tid = threadIdx.x, lane = tid & 31, wid = tid >> 5;
    const int m0 = blockIdx.x * 128;
    const int n0 = blockIdx.y * 128;
    const int z  = blockIdx.z;
    const int aoff = z * aoff_step;
    const int coff = z * coff_step;

    const __nv_bfloat16* __restrict__ Ab = A + (size_t)m0 * lda + aoff;
    const __nv_bfloat16* __restrict__ Bb = (z ? B1 : B0) + (size_t)n0 * ldb;

    const int wm = (wid & 1) * 64;   // warp m offset
    const int wn = (wid >> 1) * 32;  // warp n offset

    // per-lane ldmatrix address components (swizzle selector is 16-row invariant)
    const int rowA = wm + (lane & 15);
    const unsigned swzA = ((unsigned)rowA >> 1) & 3;
    const unsigned aBase = (unsigned)rowA * 64;
    const unsigned aSel = lane >> 4;
    const int rowB = wn + (lane & 7) + ((lane >> 4) << 3);
    const unsigned swzB = ((unsigned)rowB >> 1) & 3;
    const unsigned bBase = (unsigned)rowB * 64;
    const unsigned bSel = (lane >> 3) & 1;

    float acc[4][4][4];
    #pragma unroll
    for (int mt = 0; mt < 4; mt++)
        #pragma unroll
        for (int nt = 0; nt < 4; nt++)
            #pragma unroll
            for (int e = 0; e < 4; e++) acc[mt][nt][e] = 0.f;

    const int KT = K >> 5;   // K/32

    auto fill = [&](int kt, int st) {
        const unsigned base = sbase + st * 16384u;
        const int kb = kt * 32;
        #pragma unroll
        for (int u = 0; u < 2; u++) {
            int idx = tid + u * 256;     // 0..511
            int r = idx >> 2, c = idx & 3;
            unsigned soff = (unsigned)r * 64 + (((unsigned)c ^ (((unsigned)r >> 1) & 3)) << 4);
            cpa16(base + soff,         Ab + (size_t)r * lda + kb + c * 8);
            cpa16(base + 8192u + soff, Bb + (size_t)r * ldb + kb + c * 8);
        }
    };

    fill(0, 0); cpcommit();
    if (KT > 1) fill(1, 1);
    cpcommit();

    for (int kt = 0; kt < KT; kt++) {
        cpwait<1>();
        __syncthreads();
        int pf = kt + 2;
        if (pf < KT) fill(pf, pf % 3);
        cpcommit();

        const unsigned As = sbase + (kt % 3) * 16384u;
        const unsigned Bs = As + 8192u;
        #pragma unroll
        for (int kk = 0; kk < 2; kk++) {
            unsigned a[4][4];
            #pragma unroll
            for (int mt = 0; mt < 4; mt++)
                ldsm4(As + aBase + mt * 1024u + ((((unsigned)(kk * 2) + aSel) ^ swzA) << 4),
                      a[mt][0], a[mt][1], a[mt][2], a[mt][3]);
            unsigned b[4][2];
            #pragma unroll
            for (int g = 0; g < 2; g++) {
                unsigned r0, r1, r2, r3;
                ldsm4(Bs + bBase + g * 1024u + ((((unsigned)(kk * 2) + bSel) ^ swzB) << 4),
                      r0, r1, r2, r3);
                b[g * 2][0] = r0; b[g * 2][1] = r1;
                b[g * 2 + 1][0] = r2; b[g * 2 + 1][1] = r3;
            }
            #pragma unroll
            for (int mt = 0; mt < 4; mt++)
                #pragma unroll
                for (int nt = 0; nt < 4; nt++)
                    mma16816(acc[mt][nt], a[mt], b[nt]);
        }
        __syncthreads();
    }

    // epilogue
    const int gid = lane >> 2;        // 0..7
    const int tg  = (lane & 3) * 2;   // 0,2,4,6
    if (OUTBF16) {
        __nv_bfloat16* C = (__nv_bfloat16*)Cv;
        #pragma unroll
        for (int mt = 0; mt < 4; mt++) {
            int r = m0 + wm + mt * 16 + gid;
            #pragma unroll
            for (int nt = 0; nt < 4; nt++) {
                int col = coff + n0 + wn + nt * 8 + tg;
                *(unsigned*)(C + (size_t)r * ldc + col)       = pk_bf16x2(acc[mt][nt][0], acc[mt][nt][1]);
                *(unsigned*)(C + (size_t)(r + 8) * ldc + col) = pk_bf16x2(acc[mt][nt][2], acc[mt][nt][3]);
            }
        }
    } else {
        float* C = (float*)Cv;
        #pragma unroll
        for (int mt = 0; mt < 4; mt++) {
            int r = m0 + wm + mt * 16 + gid;
            #pragma unroll
            for (int nt = 0; nt < 4; nt++) {
                int col = coff + n0 + wn + nt * 8 + tg;
                *(float2*)(C + (size_t)r * ldc + col)       = make_float2(acc[mt][nt][0], acc[mt][nt][1]);
                *(float2*)(C + (size_t)(r + 8) * ldc + col) = make_float2(acc[mt][nt][2], acc[mt][nt][3]);
            }
        }
    }
}

// ================= warp-per-token top-k =================
__global__ __launch_bounds__(256) void topk_warp(
    const float* __restrict__ scores,
    float* __restrict__ wts, int* __restrict__ idxs, int NT)
{
    const int lane = threadIdx.x & 31;
    const int t = blockIdx.x * 8 + (threadIdx.x >> 5);
    if (t >= NT) return;
    const float* row = scores + (size_t)t * (2 * N_SUB);

    float va[8], vb[8];
    {
        float4 p0 = *(const float4*)(row + lane * 8);
        float4 p1 = *(const float4*)(row + lane * 8 + 4);
        va[0] = p0.x; va[1] = p0.y; va[2] = p0.z; va[3] = p0.w;
        va[4] = p1.x; va[5] = p1.y; va[6] = p1.z; va[7] = p1.w;
        float4 q0 = *(const float4*)(row + 256 + lane * 8);
        float4 q1 = *(const float4*)(row + 256 + lane * 8 + 4);
        vb[0] = q0.x; vb[1] = q0.y; vb[2] = q0.z; vb[3] = q0.w;
        vb[4] = q1.x; vb[5] = q1.y; vb[6] = q1.z; vb[7] = q1.w;
    }

    float ta_v = 0.f, tb_v = 0.f;
    int   ta_i = 0,   tb_i = 0;

    #pragma unroll
    for (int it = 0; it < TOPK; it++) {
        float bv = va[0]; int bs = 0;
        #pragma unroll
        for (int s = 1; s < 8; s++) if (va[s] > bv) { bv = va[s]; bs = s; }
        int bi = lane * 8 + bs;
        #pragma unroll
        for (int off = 16; off; off >>= 1) {
            float ov = __shfl_down_sync(0xffffffffu, bv, off);
            int   oi = __shfl_down_sync(0xffffffffu, bi, off);
            if (ov > bv || (ov == bv && oi < bi)) { bv = ov; bi = oi; }
        }
        bv = __shfl_sync(0xffffffffu, bv, 0);
        bi = __shfl_sync(0xffffffffu, bi, 0);
        if (lane == it) { ta_v = bv; ta_i = bi; }
        if ((bi >> 3) == lane) {
            int s0 = bi & 7;
            #pragma unroll
            for (int s = 0; s < 8; s++) if (s == s0) va[s] = -INFINITY;
        }
    }
    #pragma unroll
    for (int it = 0; it < TOPK; it++) {
        float bv = vb[0]; int bs = 0;
        #pragma unroll
        for (int s = 1; s < 8; s++) if (vb[s] > bv) { bv = vb[s]; bs = s; }
        int bi = lane * 8 + bs;
        #pragma unroll
        for (int off = 16; off; off >>= 1) {
            float ov = __shfl_down_sync(0xffffffffu, bv, off);
            int   oi = __shfl_down_sync(0xffffffffu, bi, off);
            if (ov > bv || (ov == bv && oi < bi)) { bv = ov; bi = oi; }
        }
        bv = __shfl_sync(0xffffffffu, bv, 0);
        bi = __shfl_sync(0xffffffffu, bi, 0);
        if (lane == it) { tb_v = bv; tb_i = bi; }
        if ((bi >> 3) == lane) {
            int s0 = bi & 7;
            #pragma unroll
            for (int s = 0; s < 8; s++) if (s == s0) vb[s] = -INFINITY;
        }
    }

    float a0v = __shfl_sync(0xffffffffu, ta_v, lane >> 3);
    float a1v = __shfl_sync(0xffffffffu, ta_v, (lane >> 3) + 4);
    int   a0i = __shfl_sync(0xffffffffu, ta_i, lane >> 3);
    int   a1i = __shfl_sync(0xffffffffu, ta_i, (lane >> 3) + 4);
    float bbv = __shfl_sync(0xffffffffu, tb_v, lane & 7);
    int   bbi = __shfl_sync(0xffffffffu, tb_i, lane & 7);

    float cv0 = a0v + bbv;  int ci0 = a0i * N_SUB + bbi;
    float cv1 = a1v + bbv;  int ci1 = a1i * N_SUB + bbi;

    float fv = 0.f; int fidx = 0;
    #pragma unroll
    for (int it = 0; it < TOPK; it++) {
        float bv; int bp, bi;
        if (cv1 > cv0) { bv = cv1; bp = lane + 32; bi = ci1; }
        else           { bv = cv0; bp = lane;      bi = ci0; }
        #pragma unroll
        for (int off = 16; off; off >>= 1) {
            float ov = __shfl_down_sync(0xffffffffu, bv, off);
            int   op = __shfl_down_sync(0xffffffffu, bp, off);
            int   oi = __shfl_down_sync(0xffffffffu, bi, off);
            if (ov > bv || (ov == bv && op < bp)) { bv = ov; bp = op; bi = oi; }
        }
        bv = __shfl_sync(0xffffffffu, bv, 0);
        bp = __shfl_sync(0xffffffffu, bp, 0);
        bi = __shfl_sync(0xffffffffu, bi, 0);
        if (lane == it) { fv = bv; fidx = bi; }
        if (bp == lane)      cv0 = -INFINITY;
        if (bp == lane + 32) cv1 = -INFINITY;
    }

    float fmaxv = __shfl_sync(0xffffffffu, fv, 0);
    float e = (lane < TOPK) ? expf(fv - fmaxv) : 0.f;
    float ssum = e;
    #pragma unroll
    for (int off = 16; off; off >>= 1) ssum += __shfl_xor_sync(0xffffffffu, ssum, off);
    if (lane < TOPK) {
        wts[(size_t)t * TOPK + lane]  = e / ssum;
        idxs[(size_t)t * TOPK + lane] = fidx;
    }
}

// ================= gather + gate + residual =================
__global__ __launch_bounds__(256) void gather_kernel(
    const float* __restrict__ x, const float* __restrict__ values,
    const float* __restrict__ gate_w, const float* __restrict__ gate_b,
    const float* __restrict__ wts, const int* __restrict__ idxs,
    float* __restrict__ out)
{
    const int t = blockIdx.x;
    const int tid = threadIdx.x;
    const int lane = tid & 31, wid = tid >> 5;

    const float4* xr = (const float4*)(x + (size_t)t * D_MODEL);
    const float4* gw = (const float4*)gate_w;

    float4 xv = xr[tid];
    float4 gv = gw[tid];
    float p = xv.x * gv.x + xv.y * gv.y + xv.z * gv.z + xv.w * gv.w;
    #pragma unroll
    for (int off = 16; off; off >>= 1) p += __shfl_down_sync(0xffffffffu, p, off);

    __shared__ float red[8];
    __shared__ float sw[TOPK];
    __shared__ int   sid[TOPK];
    __shared__ float sg;
    if (lane == 0) red[wid] = p;
    if (tid >= 32 && tid < 32 + TOPK) {
        sw[tid - 32]  = wts[(size_t)t * TOPK + (tid - 32)];
        sid[tid - 32] = idxs[(size_t)t * TOPK + (tid - 32)];
    }
    __syncthreads();
    if (tid == 0) {
        float s = red[0];
        #pragma unroll
        for (int w = 1; w < 8; w++) s += red[w];
        sg = 1.f / (1.f + expf(-(s + gate_b[0])));
    }
    __syncthreads();
    const float g = sg;

    float4 acc = make_float4(0.f, 0.f, 0.f, 0.f);
    #pragma unroll
    for (int k = 0; k < TOPK; k++) {
        const float4* vr = (const float4*)(values + (size_t)sid[k] * D_MODEL);
        float4 vv = __ldg(vr + tid);
        float w = sw[k];
        acc.x += w * vv.x; acc.y += w * vv.y; acc.z += w * vv.z; acc.w += w * vv.w;
    }
    float4 o;
    o.x = xv.x + g * acc.x;
    o.y = xv.y + g * acc.y;
    o.z = xv.z + g * acc.z;
    o.w = xv.w + g * acc.w;
    ((float4*)(out + (size_t)t * D_MODEL))[tid] = o;
}

// ================= launch =================
extern "C" void kernel_launch(void* const* d_in, const int* in_sizes, int n_in,
                              void* d_out, int out_size)
{
    const float* x      = (const float*)d_in[0];
    const float* keys_a = (const float*)d_in[1];
    const float* keys_b = (const float*)d_in[2];
    const float* values = (const float*)d_in[3];
    const float* Wq     = (const float*)d_in[4];
    const float* gate_w = (const float*)d_in[5];
    const float* gate_b = (const float*)d_in[6];
    float* out = (float*)d_out;

    const int NT = in_sizes[0] / D_MODEL;   // 8192

    __nv_bfloat16 *xb, *wqb, *kbb, *qb;
    float *sbuf, *wbuf; int *ibuf;
    cudaGetSymbolAddress((void**)&xb,   g_xb);
    cudaGetSymbolAddress((void**)&wqb,  g_wqb);
    cudaGetSymbolAddress((void**)&kbb,  g_kb);
    cudaGetSymbolAddress((void**)&qb,   g_qb);
    cudaGetSymbolAddress((void**)&sbuf, g_scores);
    cudaGetSymbolAddress((void**)&wbuf, g_wts);
    cudaGetSymbolAddress((void**)&ibuf, g_idx);

    // 0) convert inputs to bf16
    {
        int X4 = NT * D_MODEL / 4;
        int total = X4 + (2 * D_KEY * D_MODEL) / 4 + 2 * (N_SUB * D_KEY) / 4;
        convert_kernel<<<(total + 255) / 256, 256>>>(
            (const float4*)x, (const float4*)Wq, (const float4*)keys_a, (const float4*)keys_b,
            (uint2*)xb, (uint2*)wqb, (uint2*)kbb, X4);
    }
    // 1) q = x @ Wq^T : [NT,1024] x [256,1024]^T -> bf16 [NT,256]
    {
        dim3 grid(NT / 128, (2 * D_KEY) / 128, 1);
        hmma_gemm<true><<<grid, 256>>>(xb, D_MODEL, 0, wqb, wqb, D_MODEL,
                                       qb, 2 * D_KEY, 0, D_MODEL);
    }
    // 2) scores = q @ keys^T (both halves via grid.z) -> fp32 [NT,512]
    {
        dim3 grid(NT / 128, N_SUB / 128, 2);
        hmma_gemm<false><<<grid, 256>>>(qb, 2 * D_KEY, D_KEY,
                                        kbb, kbb + N_SUB * D_KEY, D_KEY,
                                        sbuf, 2 * N_SUB, N_SUB, D_KEY);
    }
    // 3) top-k + softmax
    topk_warp<<<(NT + 7) / 8, 256>>>(sbuf, wbuf, ibuf, NT);
    // 4) gather + gate + residual
    gather_kernel<<<NT, 256>>>(x, values, gate_w, gate_b, wbuf, ibuf, out);
}

// round 5
// speedup vs baseline: 3.0701x; 1.1306x over previous
#include <cuda_runtime.h>
#include <cuda_bf16.h>
#include <math.h>

#define D_MODEL 1024
#define D_KEY   128
#define N_SUB   256
#define TOPK    8
#define MAXNT   8192

// -------- scratch (device globals) --------
__device__ __align__(128) __nv_bfloat16 g_xb [MAXNT * D_MODEL];
__device__ __align__(128) __nv_bfloat16 g_wqb[2 * D_KEY * D_MODEL];
__device__ __align__(128) __nv_bfloat16 g_kb [2 * N_SUB * D_KEY];
__device__ __align__(128) __nv_bfloat16 g_qb [MAXNT * 2 * D_KEY];
__device__ __align__(128) float g_scores[MAXNT * 2 * N_SUB];
__device__ float g_wts[MAXNT * TOPK];
__device__ int   g_idx[MAXNT * TOPK];

// ================= base-PTX helpers =================
__device__ __forceinline__ unsigned smem_u32(const void* p) {
    unsigned a;
    asm("{ .reg .u64 t; cvta.to.shared.u64 t, %1; cvt.u32.u64 %0, t; }" : "=r"(a) : "l"(p));
    return a;
}
__device__ __forceinline__ void cpa16(unsigned d, const void* s) {
    asm volatile("cp.async.cg.shared.global [%0], [%1], 16;" :: "r"(d), "l"(s));
}
__device__ __forceinline__ void cpcommit() { asm volatile("cp.async.commit_group;" ::: "memory"); }
template<int N> __device__ __forceinline__ void cpwait() {
    asm volatile("cp.async.wait_group %0;" :: "n"(N) : "memory");
}
__device__ __forceinline__ void ldsm4(unsigned addr, unsigned& r0, unsigned& r1,
                                      unsigned& r2, unsigned& r3) {
    asm volatile("ldmatrix.sync.aligned.m8n8.x4.shared.b16 {%0,%1,%2,%3}, [%4];"
                 : "=r"(r0), "=r"(r1), "=r"(r2), "=r"(r3) : "r"(addr));
}
__device__ __forceinline__ void mma16816(float* c, const unsigned* a, const unsigned* b) {
    asm volatile("mma.sync.aligned.m16n8k16.row.col.f32.bf16.bf16.f32 "
                 "{%0,%1,%2,%3}, {%4,%5,%6,%7}, {%8,%9}, {%0,%1,%2,%3};"
                 : "+f"(c[0]), "+f"(c[1]), "+f"(c[2]), "+f"(c[3])
                 : "r"(a[0]), "r"(a[1]), "r"(a[2]), "r"(a[3]), "r"(b[0]), "r"(b[1]));
}
__device__ __forceinline__ unsigned pk_bf16x2(float a, float b) {
    __nv_bfloat162 h = __floats2bfloat162_rn(a, b);
    return *(unsigned*)&h;
}
// order-preserving float<->uint
__device__ __forceinline__ unsigned fmono(float f) {
    unsigned u = __float_as_uint(f);
    return u ^ (((unsigned)((int)u >> 31)) | 0x80000000u);
}
__device__ __forceinline__ float funmono(unsigned m) {
    unsigned u = (m & 0x80000000u) ? (m ^ 0x80000000u) : ~m;
    return __uint_as_float(u);
}

// ================= convert fp32 -> bf16 (x, Wq, keys) =================
__global__ __launch_bounds__(256) void convert_kernel(
    const float4* __restrict__ x, const float4* __restrict__ wq,
    const float4* __restrict__ ka, const float4* __restrict__ kb,
    uint2* __restrict__ xb, uint2* __restrict__ wqb, uint2* __restrict__ kbb,
    int X4)
{
    const int W4 = (2 * D_KEY * D_MODEL) / 4;
    const int K4 = (N_SUB * D_KEY) / 4;
    int i = blockIdx.x * blockDim.x + threadIdx.x;
    float4 v; uint2 o;
    if (i < X4) {
        v = x[i];
        o.x = pk_bf16x2(v.x, v.y); o.y = pk_bf16x2(v.z, v.w);
        xb[i] = o;
    } else if (i < X4 + W4) {
        int j = i - X4; v = wq[j];
        o.x = pk_bf16x2(v.x, v.y); o.y = pk_bf16x2(v.z, v.w);
        wqb[j] = o;
    } else if (i < X4 + W4 + K4) {
        int j = i - X4 - W4; v = ka[j];
        o.x = pk_bf16x2(v.x, v.y); o.y = pk_bf16x2(v.z, v.w);
        kbb[j] = o;
    } else if (i < X4 + W4 + 2 * K4) {
        int j = i - X4 - W4 - K4; v = kb[j];
        o.x = pk_bf16x2(v.x, v.y); o.y = pk_bf16x2(v.z, v.w);
        kbb[K4 + j] = o;
    }
}

// ================= HMMA GEMM (as R4) =================
template<bool OUTBF16>
__global__ __launch_bounds__(256) void hmma_gemm(
    const __nv_bfloat16* __restrict__ A, int lda, int aoff_step,
    const __nv_bfloat16* __restrict__ B0, const __nv_bfloat16* __restrict__ B1, int ldb,
    void* __restrict__ Cv, int ldc, int coff_step, int K)
{
    __shared__ __align__(128) char smem[3 * 16384];
    const unsigned sbase = smem_u32(smem);

    const int tid = threadIdx.x, lane = tid & 31, wid = tid >> 5;
    const int m0 = blockIdx.x * 128;
    const int n0 = blockIdx.y * 128;
    const int z  = blockIdx.z;
    const int aoff = z * aoff_step;
    const int coff = z * coff_step;

    const __nv_bfloat16* __restrict__ Ab = A + (size_t)m0 * lda + aoff;
    const __nv_bfloat16* __restrict__ Bb = (z ? B1 : B0) + (size_t)n0 * ldb;

    const int wm = (wid & 1) * 64;
    const int wn = (wid >> 1) * 32;

    const int rowA = wm + (lane & 15);
    const unsigned swzA = ((unsigned)rowA >> 1) & 3;
    const unsigned aBase = (unsigned)rowA * 64;
    const unsigned aSel = lane >> 4;
    const int rowB = wn + (lane & 7) + ((lane >> 4) << 3);
    const unsigned swzB = ((unsigned)rowB >> 1) & 3;
    const unsigned bBase = (unsigned)rowB * 64;
    const unsigned bSel = (lane >> 3) & 1;

    float acc[4][4][4];
    #pragma unroll
    for (int mt = 0; mt < 4; mt++)
        #pragma unroll
        for (int nt = 0; nt < 4; nt++)
            #pragma unroll
            for (int e = 0; e < 4; e++) acc[mt][nt][e] = 0.f;

    const int KT = K >> 5;

    auto fill = [&](int kt, int st) {
        const unsigned base = sbase + st * 16384u;
        const int kb = kt * 32;
        #pragma unroll
        for (int u = 0; u < 2; u++) {
            int idx = tid + u * 256;
            int r = idx >> 2, c = idx & 3;
            unsigned soff = (unsigned)r * 64 + (((unsigned)c ^ (((unsigned)r >> 1) & 3)) << 4);
            cpa16(base + soff,         Ab + (size_t)r * lda + kb + c * 8);
            cpa16(base + 8192u + soff, Bb + (size_t)r * ldb + kb + c * 8);
        }
    };

    fill(0, 0); cpcommit();
    if (KT > 1) fill(1, 1);
    cpcommit();

    for (int kt = 0; kt < KT; kt++) {
        cpwait<1>();
        __syncthreads();
        int pf = kt + 2;
        if (pf < KT) fill(pf, pf % 3);
        cpcommit();

        const unsigned As = sbase + (kt % 3) * 16384u;
        const unsigned Bs = As + 8192u;
        #pragma unroll
        for (int kk = 0; kk < 2; kk++) {
            unsigned a[4][4];
            #pragma unroll
            for (int mt = 0; mt < 4; mt++)
                ldsm4(As + aBase + mt * 1024u + ((((unsigned)(kk * 2) + aSel) ^ swzA) << 4),
                      a[mt][0], a[mt][1], a[mt][2], a[mt][3]);
            unsigned b[4][2];
            #pragma unroll
            for (int g = 0; g < 2; g++) {
                unsigned r0, r1, r2, r3;
                ldsm4(Bs + bBase + g * 1024u + ((((unsigned)(kk * 2) + bSel) ^ swzB) << 4),
                      r0, r1, r2, r3);
                b[g * 2][0] = r0; b[g * 2][1] = r1;
                b[g * 2 + 1][0] = r2; b[g * 2 + 1][1] = r3;
            }
            #pragma unroll
            for (int mt = 0; mt < 4; mt++)
                #pragma unroll
                for (int nt = 0; nt < 4; nt++)
                    mma16816(acc[mt][nt], a[mt], b[nt]);
        }
        __syncthreads();
    }

    const int gid = lane >> 2;
    const int tg  = (lane & 3) * 2;
    if (OUTBF16) {
        __nv_bfloat16* C = (__nv_bfloat16*)Cv;
        #pragma unroll
        for (int mt = 0; mt < 4; mt++) {
            int r = m0 + wm + mt * 16 + gid;
            #pragma unroll
            for (int nt = 0; nt < 4; nt++) {
                int col = coff + n0 + wn + nt * 8 + tg;
                *(unsigned*)(C + (size_t)r * ldc + col)       = pk_bf16x2(acc[mt][nt][0], acc[mt][nt][1]);
                *(unsigned*)(C + (size_t)(r + 8) * ldc + col) = pk_bf16x2(acc[mt][nt][2], acc[mt][nt][3]);
            }
        }
    } else {
        float* C = (float*)Cv;
        #pragma unroll
        for (int mt = 0; mt < 4; mt++) {
            int r = m0 + wm + mt * 16 + gid;
            #pragma unroll
            for (int nt = 0; nt < 4; nt++) {
                int col = coff + n0 + wn + nt * 8 + tg;
                *(float2*)(C + (size_t)r * ldc + col)       = make_float2(acc[mt][nt][0], acc[mt][nt][1]);
                *(float2*)(C + (size_t)(r + 8) * ldc + col) = make_float2(acc[mt][nt][2], acc[mt][nt][3]);
            }
        }
    }
}

// ================= warp-per-token top-k, packed 32-bit sort keys =================
__global__ __launch_bounds__(256) void topk_warp(
    const float* __restrict__ scores,
    float* __restrict__ wts, int* __restrict__ idxs, int NT)
{
    const unsigned FULL = 0xffffffffu;
    const int lane = threadIdx.x & 31;
    const int t = blockIdx.x * 8 + (threadIdx.x >> 5);
    if (t >= NT) return;
    const float* row = scores + (size_t)t * (2 * N_SUB);

    // pack: key = (mono(v) & 0xFFFFFF00) | (255 - idx)   (max-key == argmax, lower idx wins ties)
    unsigned ka[8], kb[8];
    {
        float4 p0 = *(const float4*)(row + lane * 8);
        float4 p1 = *(const float4*)(row + lane * 8 + 4);
        float4 q0 = *(const float4*)(row + 256 + lane * 8);
        float4 q1 = *(const float4*)(row + 256 + lane * 8 + 4);
        float fa[8] = {p0.x, p0.y, p0.z, p0.w, p1.x, p1.y, p1.z, p1.w};
        float fb[8] = {q0.x, q0.y, q0.z, q0.w, q1.x, q1.y, q1.z, q1.w};
        #pragma unroll
        for (int s = 0; s < 8; s++) {
            unsigned tag = 255u - (unsigned)(lane * 8 + s);
            ka[s] = (fmono(fa[s]) & 0xFFFFFF00u) | tag;
            kb[s] = (fmono(fb[s]) & 0xFFFFFF00u) | tag;
        }
    }

    unsigned myA = 0u, myB = 0u;   // lane j (j<8) ends holding j-th winner
    #pragma unroll
    for (int it = 0; it < TOPK; it++) {
        unsigned loc = ka[0];
        #pragma unroll
        for (int s = 1; s < 8; s++) loc = max(loc, ka[s]);
        #pragma unroll
        for (int off = 16; off; off >>= 1) loc = max(loc, __shfl_xor_sync(FULL, loc, off));
        if (lane == it) myA = loc;
        #pragma unroll
        for (int s = 0; s < 8; s++) if (ka[s] == loc) ka[s] = 0u;
    }
    #pragma unroll
    for (int it = 0; it < TOPK; it++) {
        unsigned loc = kb[0];
        #pragma unroll
        for (int s = 1; s < 8; s++) loc = max(loc, kb[s]);
        #pragma unroll
        for (int off = 16; off; off >>= 1) loc = max(loc, __shfl_xor_sync(FULL, loc, off));
        if (lane == it) myB = loc;
        #pragma unroll
        for (int s = 0; s < 8; s++) if (kb[s] == loc) kb[s] = 0u;
    }

    // 64 cartesian candidates; lane owns combos pos=lane and pos=lane+32 (pos = a*8+b)
    unsigned a0k = __shfl_sync(FULL, myA, lane >> 3);
    unsigned a1k = __shfl_sync(FULL, myA, (lane >> 3) + 4);
    unsigned bk  = __shfl_sync(FULL, myB, lane & 7);
    float bvf = funmono(bk & 0xFFFFFF00u);
    float c0 = funmono(a0k & 0xFFFFFF00u) + bvf;
    float c1 = funmono(a1k & 0xFFFFFF00u) + bvf;
    int ib  = 255 - (int)(bk & 255u);
    int idx0 = (255 - (int)(a0k & 255u)) * N_SUB + ib;
    int idx1 = (255 - (int)(a1k & 255u)) * N_SUB + ib;
    unsigned k0 = (fmono(c0) & ~63u) | (63u - (unsigned)lane);
    unsigned k1 = (fmono(c1) & ~63u) | (63u - (unsigned)(lane + 32));

    unsigned fkey = 0u; int fid = 0;
    #pragma unroll
    for (int it = 0; it < TOPK; it++) {
        unsigned loc = max(k0, k1);
        #pragma unroll
        for (int off = 16; off; off >>= 1) loc = max(loc, __shfl_xor_sync(FULL, loc, off));
        unsigned pos = 63u - (loc & 63u);     // uniform across warp
        int src = (int)(pos & 31u);
        int widx = (pos < 32u) ? __shfl_sync(FULL, idx0, src)
                               : __shfl_sync(FULL, idx1, src);
        if (lane == it) { fkey = loc; fid = widx; }
        if (k0 == loc) k0 = 0u;
        if (k1 == loc) k1 = 0u;
    }

    // softmax over winners (lanes 0..7 hold them, descending)
    float val = funmono(fkey & ~63u);
    float v0 = __shfl_sync(FULL, val, 0);
    float e = (lane < TOPK) ? expf(val - v0) : 0.f;
    float ssum = e;
    #pragma unroll
    for (int off = 16; off; off >>= 1) ssum += __shfl_xor_sync(FULL, ssum, off);
    if (lane < TOPK) {
        wts[(size_t)t * TOPK + lane]  = e / ssum;
        idxs[(size_t)t * TOPK + lane] = fid;
    }
}

// ================= gather + gate + residual =================
__global__ __launch_bounds__(256) void gather_kernel(
    const float* __restrict__ x, const float* __restrict__ values,
    const float* __restrict__ gate_w, const float* __restrict__ gate_b,
    const float* __restrict__ wts, const int* __restrict__ idxs,
    float* __restrict__ out)
{
    const int t = blockIdx.x;
    const int tid = threadIdx.x;
    const int lane = tid & 31, wid = tid >> 5;

    const float4* xr = (const float4*)(x + (size_t)t * D_MODEL);
    const float4* gw = (const float4*)gate_w;

    float4 xv = xr[tid];
    float4 gv = gw[tid];
    float p = xv.x * gv.x + xv.y * gv.y + xv.z * gv.z + xv.w * gv.w;
    #pragma unroll
    for (int off = 16; off; off >>= 1) p += __shfl_down_sync(0xffffffffu, p, off);

    __shared__ float red[8];
    __shared__ float sw[TOPK];
    __shared__ int   sid[TOPK];
    __shared__ float sg;
    if (lane == 0) red[wid] = p;
    if (tid >= 32 && tid < 32 + TOPK) {
        sw[tid - 32]  = wts[(size_t)t * TOPK + (tid - 32)];
        sid[tid - 32] = idxs[(size_t)t * TOPK + (tid - 32)];
    }
    __syncthreads();
    if (tid == 0) {
        float s = red[0];
        #pragma unroll
        for (int w = 1; w < 8; w++) s += red[w];
        sg = 1.f / (1.f + expf(-(s + gate_b[0])));
    }
    __syncthreads();
    const float g = sg;

    float4 acc = make_float4(0.f, 0.f, 0.f, 0.f);
    #pragma unroll
    for (int k = 0; k < TOPK; k++) {
        const float4* vr = (const float4*)(values + (size_t)sid[k] * D_MODEL);
        float4 vv = __ldg(vr + tid);
        float w = sw[k];
        acc.x += w * vv.x; acc.y += w * vv.y; acc.z += w * vv.z; acc.w += w * vv.w;
    }
    float4 o;
    o.x = xv.x + g * acc.x;
    o.y = xv.y + g * acc.y;
    o.z = xv.z + g * acc.z;
    o.w = xv.w + g * acc.w;
    ((float4*)(out + (size_t)t * D_MODEL))[tid] = o;
}

// ================= launch =================
extern "C" void kernel_launch(void* const* d_in, const int* in_sizes, int n_in,
                              void* d_out, int out_size)
{
    const float* x      = (const float*)d_in[0];
    const float* keys_a = (const float*)d_in[1];
    const float* keys_b = (const float*)d_in[2];
    const float* values = (const float*)d_in[3];
    const float* Wq     = (const float*)d_in[4];
    const float* gate_w = (const float*)d_in[5];
    const float* gate_b = (const float*)d_in[6];
    float* out = (float*)d_out;

    const int NT = in_sizes[0] / D_MODEL;   // 8192

    __nv_bfloat16 *xb, *wqb, *kbb, *qb;
    float *sbuf, *wbuf; int *ibuf;
    cudaGetSymbolAddress((void**)&xb,   g_xb);
    cudaGetSymbolAddress((void**)&wqb,  g_wqb);
    cudaGetSymbolAddress((void**)&kbb,  g_kb);
    cudaGetSymbolAddress((void**)&qb,   g_qb);
    cudaGetSymbolAddress((void**)&sbuf, g_scores);
    cudaGetSymbolAddress((void**)&wbuf, g_wts);
    cudaGetSymbolAddress((void**)&ibuf, g_idx);

    // 0) convert inputs to bf16
    {
        int X4 = NT * D_MODEL / 4;
        int total = X4 + (2 * D_KEY * D_MODEL) / 4 + 2 * (N_SUB * D_KEY) / 4;
        convert_kernel<<<(total + 255) / 256, 256>>>(
            (const float4*)x, (const float4*)Wq, (const float4*)keys_a, (const float4*)keys_b,
            (uint2*)xb, (uint2*)wqb, (uint2*)kbb, X4);
    }
    // 1) q = x @ Wq^T -> bf16 [NT,256]
    {
        dim3 grid(NT / 128, (2 * D_KEY) / 128, 1);
        hmma_gemm<true><<<grid, 256>>>(xb, D_MODEL, 0, wqb, wqb, D_MODEL,
                                       qb, 2 * D_KEY, 0, D_MODEL);
    }
    // 2) scores = q @ keys^T (both halves via grid.z) -> fp32 [NT,512]
    {
        dim3 grid(NT / 128, N_SUB / 128, 2);
        hmma_gemm<false><<<grid, 256>>>(qb, 2 * D_KEY, D_KEY,
                                        kbb, kbb + N_SUB * D_KEY, D_KEY,
                                        sbuf, 2 * N_SUB, N_SUB, D_KEY);
    }
    // 3) top-k + softmax
    topk_warp<<<(NT + 7) / 8, 256>>>(sbuf, wbuf, ibuf, NT);
    // 4) gather + gate + residual
    gather_kernel<<<NT, 256>>>(x, values, gate_w, gate_b, wbuf, ibuf, out);
}

// round 6
// speedup vs baseline: 3.1899x; 1.0390x over previous
#include <cuda_runtime.h>
#include <cuda_bf16.h>
#include <math.h>

#define D_MODEL 1024
#define D_KEY   128
#define N_SUB   256
#define TOPK    8
#define MAXNT   8192

// -------- scratch (device globals) --------
__device__ __align__(128) __nv_bfloat16 g_xb [MAXNT * D_MODEL];
__device__ __align__(128) __nv_bfloat16 g_wqb[2 * D_KEY * D_MODEL];
__device__ __align__(128) __nv_bfloat16 g_kb [2 * N_SUB * D_KEY];
__device__ __align__(128) __nv_bfloat16 g_qb [MAXNT * 2 * D_KEY];
__device__ __align__(128) float g_scores[MAXNT * 2 * N_SUB];
__device__ float g_wts[MAXNT * TOPK];
__device__ int   g_idx[MAXNT * TOPK];

// ================= base-PTX helpers =================
__device__ __forceinline__ unsigned smem_u32(const void* p) {
    unsigned a;
    asm("{ .reg .u64 t; cvta.to.shared.u64 t, %1; cvt.u32.u64 %0, t; }" : "=r"(a) : "l"(p));
    return a;
}
__device__ __forceinline__ void cpa16(unsigned d, const void* s) {
    asm volatile("cp.async.cg.shared.global [%0], [%1], 16;" :: "r"(d), "l"(s));
}
__device__ __forceinline__ void cpcommit() { asm volatile("cp.async.commit_group;" ::: "memory"); }
template<int N> __device__ __forceinline__ void cpwait() {
    asm volatile("cp.async.wait_group %0;" :: "n"(N) : "memory");
}
__device__ __forceinline__ void ldsm4(unsigned addr, unsigned& r0, unsigned& r1,
                                      unsigned& r2, unsigned& r3) {
    asm volatile("ldmatrix.sync.aligned.m8n8.x4.shared.b16 {%0,%1,%2,%3}, [%4];"
                 : "=r"(r0), "=r"(r1), "=r"(r2), "=r"(r3) : "r"(addr));
}
__device__ __forceinline__ void mma16816(float* c, const unsigned* a, const unsigned* b) {
    asm volatile("mma.sync.aligned.m16n8k16.row.col.f32.bf16.bf16.f32 "
                 "{%0,%1,%2,%3}, {%4,%5,%6,%7}, {%8,%9}, {%0,%1,%2,%3};"
                 : "+f"(c[0]), "+f"(c[1]), "+f"(c[2]), "+f"(c[3])
                 : "r"(a[0]), "r"(a[1]), "r"(a[2]), "r"(a[3]), "r"(b[0]), "r"(b[1]));
}
__device__ __forceinline__ unsigned pk_bf16x2(float a, float b) {
    __nv_bfloat162 h = __floats2bfloat162_rn(a, b);
    return *(unsigned*)&h;
}
__device__ __forceinline__ unsigned fmono(float f) {
    unsigned u = __float_as_uint(f);
    return u ^ (((unsigned)((int)u >> 31)) | 0x80000000u);
}
__device__ __forceinline__ float funmono(unsigned m) {
    unsigned u = (m & 0x80000000u) ? (m ^ 0x80000000u) : ~m;
    return __uint_as_float(u);
}
__device__ __forceinline__ unsigned redux_max(unsigned v) {
    unsigned d;
    asm volatile("redux.sync.max.u32 %0, %1, 0xffffffff;" : "=r"(d) : "r"(v));
    return d;
}

// ================= convert fp32 -> bf16 (x, Wq, keys) =================
__global__ __launch_bounds__(256) void convert_kernel(
    const float4* __restrict__ x, const float4* __restrict__ wq,
    const float4* __restrict__ ka, const float4* __restrict__ kb,
    uint2* __restrict__ xb, uint2* __restrict__ wqb, uint2* __restrict__ kbb,
    int X4)
{
    const int W4 = (2 * D_KEY * D_MODEL) / 4;
    const int K4 = (N_SUB * D_KEY) / 4;
    int i = blockIdx.x * blockDim.x + threadIdx.x;
    float4 v; uint2 o;
    if (i < X4) {
        v = x[i];
        o.x = pk_bf16x2(v.x, v.y); o.y = pk_bf16x2(v.z, v.w);
        xb[i] = o;
    } else if (i < X4 + W4) {
        int j = i - X4; v = wq[j];
        o.x = pk_bf16x2(v.x, v.y); o.y = pk_bf16x2(v.z, v.w);
        wqb[j] = o;
    } else if (i < X4 + W4 + K4) {
        int j = i - X4 - W4; v = ka[j];
        o.x = pk_bf16x2(v.x, v.y); o.y = pk_bf16x2(v.z, v.w);
        kbb[j] = o;
    } else if (i < X4 + W4 + 2 * K4) {
        int j = i - X4 - W4 - K4; v = kb[j];
        o.x = pk_bf16x2(v.x, v.y); o.y = pk_bf16x2(v.z, v.w);
        kbb[K4 + j] = o;
    }
}

// ================= HMMA GEMM (as R4/R5) =================
template<bool OUTBF16>
__global__ __launch_bounds__(256) void hmma_gemm(
    const __nv_bfloat16* __restrict__ A, int lda, int aoff_step,
    const __nv_bfloat16* __restrict__ B0, const __nv_bfloat16* __restrict__ B1, int ldb,
    void* __restrict__ Cv, int ldc, int coff_step, int K)
{
    __shared__ __align__(128) char smem[3 * 16384];
    const unsigned sbase = smem_u32(smem);

    const int tid = threadIdx.x, lane = tid & 31, wid = tid >> 5;
    const int m0 = blockIdx.x * 128;
    const int n0 = blockIdx.y * 128;
    const int z  = blockIdx.z;
    const int aoff = z * aoff_step;
    const int coff = z * coff_step;

    const __nv_bfloat16* __restrict__ Ab = A + (size_t)m0 * lda + aoff;
    const __nv_bfloat16* __restrict__ Bb = (z ? B1 : B0) + (size_t)n0 * ldb;

    const int wm = (wid & 1) * 64;
    const int wn = (wid >> 1) * 32;

    const int rowA = wm + (lane & 15);
    const unsigned swzA = ((unsigned)rowA >> 1) & 3;
    const unsigned aBase = (unsigned)rowA * 64;
    const unsigned aSel = lane >> 4;
    const int rowB = wn + (lane & 7) + ((lane >> 4) << 3);
    const unsigned swzB = ((unsigned)rowB >> 1) & 3;
    const unsigned bBase = (unsigned)rowB * 64;
    const unsigned bSel = (lane >> 3) & 1;

    float acc[4][4][4];
    #pragma unroll
    for (int mt = 0; mt < 4; mt++)
        #pragma unroll
        for (int nt = 0; nt < 4; nt++)
            #pragma unroll
            for (int e = 0; e < 4; e++) acc[mt][nt][e] = 0.f;

    const int KT = K >> 5;

    auto fill = [&](int kt, int st) {
        const unsigned base = sbase + st * 16384u;
        const int kb = kt * 32;
        #pragma unroll
        for (int u = 0; u < 2; u++) {
            int idx = tid + u * 256;
            int r = idx >> 2, c = idx & 3;
            unsigned soff = (unsigned)r * 64 + (((unsigned)c ^ (((unsigned)r >> 1) & 3)) << 4);
            cpa16(base + soff,         Ab + (size_t)r * lda + kb + c * 8);
            cpa16(base + 8192u + soff, Bb + (size_t)r * ldb + kb + c * 8);
        }
    };

    fill(0, 0); cpcommit();
    if (KT > 1) fill(1, 1);
    cpcommit();

    for (int kt = 0; kt < KT; kt++) {
        cpwait<1>();
        __syncthreads();
        int pf = kt + 2;
        if (pf < KT) fill(pf, pf % 3);
        cpcommit();

        const unsigned As = sbase + (kt % 3) * 16384u;
        const unsigned Bs = As + 8192u;
        #pragma unroll
        for (int kk = 0; kk < 2; kk++) {
            unsigned a[4][4];
            #pragma unroll
            for (int mt = 0; mt < 4; mt++)
                ldsm4(As + aBase + mt * 1024u + ((((unsigned)(kk * 2) + aSel) ^ swzA) << 4),
                      a[mt][0], a[mt][1], a[mt][2], a[mt][3]);
            unsigned b[4][2];
            #pragma unroll
            for (int g = 0; g < 2; g++) {
                unsigned r0, r1, r2, r3;
                ldsm4(Bs + bBase + g * 1024u + ((((unsigned)(kk * 2) + bSel) ^ swzB) << 4),
                      r0, r1, r2, r3);
                b[g * 2][0] = r0; b[g * 2][1] = r1;
                b[g * 2 + 1][0] = r2; b[g * 2 + 1][1] = r3;
            }
            #pragma unroll
            for (int mt = 0; mt < 4; mt++)
                #pragma unroll
                for (int nt = 0; nt < 4; nt++)
                    mma16816(acc[mt][nt], a[mt], b[nt]);
        }
        __syncthreads();
    }

    const int gid = lane >> 2;
    const int tg  = (lane & 3) * 2;
    if (OUTBF16) {
        __nv_bfloat16* C = (__nv_bfloat16*)Cv;
        #pragma unroll
        for (int mt = 0; mt < 4; mt++) {
            int r = m0 + wm + mt * 16 + gid;
            #pragma unroll
            for (int nt = 0; nt < 4; nt++) {
                int col = coff + n0 + wn + nt * 8 + tg;
                *(unsigned*)(C + (size_t)r * ldc + col)       = pk_bf16x2(acc[mt][nt][0], acc[mt][nt][1]);
                *(unsigned*)(C + (size_t)(r + 8) * ldc + col) = pk_bf16x2(acc[mt][nt][2], acc[mt][nt][3]);
            }
        }
    } else {
        float* C = (float*)Cv;
        #pragma unroll
        for (int mt = 0; mt < 4; mt++) {
            int r = m0 + wm + mt * 16 + gid;
            #pragma unroll
            for (int nt = 0; nt < 4; nt++) {
                int col = coff + n0 + wn + nt * 8 + tg;
                *(float2*)(C + (size_t)r * ldc + col)       = make_float2(acc[mt][nt][0], acc[mt][nt][1]);
                *(float2*)(C + (size_t)(r + 8) * ldc + col) = make_float2(acc[mt][nt][2], acc[mt][nt][3]);
            }
        }
    }
}

// ================= warp-per-token top-k: packed keys + redux.sync =================
__global__ __launch_bounds__(256) void topk_warp(
    const float* __restrict__ scores,
    float* __restrict__ wts, int* __restrict__ idxs, int NT)
{
    const unsigned FULL = 0xffffffffu;
    const int lane = threadIdx.x & 31;
    const int t = blockIdx.x * 8 + (threadIdx.x >> 5);
    if (t >= NT) return;
    const float* row = scores + (size_t)t * (2 * N_SUB);

    unsigned ka[8], kb[8];
    {
        float4 p0 = *(const float4*)(row + lane * 8);
        float4 p1 = *(const float4*)(row + lane * 8 + 4);
        float4 q0 = *(const float4*)(row + 256 + lane * 8);
        float4 q1 = *(const float4*)(row + 256 + lane * 8 + 4);
        float fa[8] = {p0.x, p0.y, p0.z, p0.w, p1.x, p1.y, p1.z, p1.w};
        float fb[8] = {q0.x, q0.y, q0.z, q0.w, q1.x, q1.y, q1.z, q1.w};
        #pragma unroll
        for (int s = 0; s < 8; s++) {
            unsigned tag = 255u - (unsigned)(lane * 8 + s);
            ka[s] = (fmono(fa[s]) & 0xFFFFFF00u) | tag;
            kb[s] = (fmono(fb[s]) & 0xFFFFFF00u) | tag;
        }
    }

    // interleaved A/B iterated argmax: two independent chains, one redux each
    unsigned myA = 0u, myB = 0u;
    #pragma unroll
    for (int it = 0; it < TOPK; it++) {
        unsigned la = ka[0], lb = kb[0];
        #pragma unroll
        for (int s = 1; s < 8; s++) { la = max(la, ka[s]); lb = max(lb, kb[s]); }
        unsigned wa = redux_max(la);
        unsigned wb = redux_max(lb);
        if (lane == it) { myA = wa; myB = wb; }
        #pragma unroll
        for (int s = 0; s < 8; s++) {
            if (ka[s] == wa) ka[s] = 0u;
            if (kb[s] == wb) kb[s] = 0u;
        }
    }

    // 64 cartesian candidates; lane owns pos=lane and pos=lane+32 (pos = a*8+b)
    unsigned a0k = __shfl_sync(FULL, myA, lane >> 3);
    unsigned a1k = __shfl_sync(FULL, myA, (lane >> 3) + 4);
    unsigned bk  = __shfl_sync(FULL, myB, lane & 7);
    float bvf = funmono(bk & 0xFFFFFF00u);
    float c0 = funmono(a0k & 0xFFFFFF00u) + bvf;
    float c1 = funmono(a1k & 0xFFFFFF00u) + bvf;
    int ib  = 255 - (int)(bk & 255u);
    int idx0 = (255 - (int)(a0k & 255u)) * N_SUB + ib;
    int idx1 = (255 - (int)(a1k & 255u)) * N_SUB + ib;
    unsigned k0 = (fmono(c0) & ~63u) | (63u - (unsigned)lane);
    unsigned k1 = (fmono(c1) & ~63u) | (63u - (unsigned)(lane + 32));

    unsigned fkey = 0u; int fid = 0;
    #pragma unroll
    for (int it = 0; it < TOPK; it++) {
        unsigned loc = redux_max(max(k0, k1));
        unsigned pos = 63u - (loc & 63u);
        int src = (int)(pos & 31u);
        int widx = (pos < 32u) ? __shfl_sync(FULL, idx0, src)
                               : __shfl_sync(FULL, idx1, src);
        if (lane == it) { fkey = loc; fid = widx; }
        if (k0 == loc) k0 = 0u;
        if (k1 == loc) k1 = 0u;
    }

    // softmax over winners (lanes 0..7, descending -> lane 0 holds max)
    float val = funmono(fkey & ~63u);
    float v0 = __shfl_sync(FULL, val, 0);
    float e = (lane < TOPK) ? expf(val - v0) : 0.f;
    float ssum = e;
    #pragma unroll
    for (int off = 4; off; off >>= 1) ssum += __shfl_xor_sync(FULL, ssum, off);
    if (lane < TOPK) {
        wts[(size_t)t * TOPK + lane]  = e / ssum;
        idxs[(size_t)t * TOPK + lane] = fid;
    }
}

// ================= gather + gate + residual =================
__global__ __launch_bounds__(256) void gather_kernel(
    const float* __restrict__ x, const float* __restrict__ values,
    const float* __restrict__ gate_w, const float* __restrict__ gate_b,
    const float* __restrict__ wts, const int* __restrict__ idxs,
    float* __restrict__ out)
{
    const int t = blockIdx.x;
    const int tid = threadIdx.x;
    const int lane = tid & 31, wid = tid >> 5;

    const float4* xr = (const float4*)(x + (size_t)t * D_MODEL);
    const float4* gw = (const float4*)gate_w;

    float4 xv = xr[tid];
    float4 gv = gw[tid];
    float p = xv.x * gv.x + xv.y * gv.y + xv.z * gv.z + xv.w * gv.w;
    #pragma unroll
    for (int off = 16; off; off >>= 1) p += __shfl_down_sync(0xffffffffu, p, off);

    __shared__ float red[8];
    __shared__ float sw[TOPK];
    __shared__ int   sid[TOPK];
    __shared__ float sg;
    if (lane == 0) red[wid] = p;
    if (tid >= 32 && tid < 32 + TOPK) {
        sw[tid - 32]  = wts[(size_t)t * TOPK + (tid - 32)];
        sid[tid - 32] = idxs[(size_t)t * TOPK + (tid - 32)];
    }
    __syncthreads();
    if (tid == 0) {
        float s = red[0];
        #pragma unroll
        for (int w = 1; w < 8; w++) s += red[w];
        sg = 1.f / (1.f + expf(-(s + gate_b[0])));
    }
    __syncthreads();
    const float g = sg;

    float4 acc = make_float4(0.f, 0.f, 0.f, 0.f);
    #pragma unroll
    for (int k = 0; k < TOPK; k++) {
        const float4* vr = (const float4*)(values + (size_t)sid[k] * D_MODEL);
        float4 vv = __ldg(vr + tid);
        float w = sw[k];
        acc.x += w * vv.x; acc.y += w * vv.y; acc.z += w * vv.z; acc.w += w * vv.w;
    }
    float4 o;
    o.x = xv.x + g * acc.x;
    o.y = xv.y + g * acc.y;
    o.z = xv.z + g * acc.z;
    o.w = xv.w + g * acc.w;
    ((float4*)(out + (size_t)t * D_MODEL))[tid] = o;
}

// ================= launch =================
extern "C" void kernel_launch(void* const* d_in, const int* in_sizes, int n_in,
                              void* d_out, int out_size)
{
    const float* x      = (const float*)d_in[0];
    const float* keys_a = (const float*)d_in[1];
    const float* keys_b = (const float*)d_in[2];
    const float* values = (const float*)d_in[3];
    const float* Wq     = (const float*)d_in[4];
    const float* gate_w = (const float*)d_in[5];
    const float* gate_b = (const float*)d_in[6];
    float* out = (float*)d_out;

    const int NT = in_sizes[0] / D_MODEL;   // 8192

    __nv_bfloat16 *xb, *wqb, *kbb, *qb;
    float *sbuf, *wbuf; int *ibuf;
    cudaGetSymbolAddress((void**)&xb,   g_xb);
    cudaGetSymbolAddress((void**)&wqb,  g_wqb);
    cudaGetSymbolAddress((void**)&kbb,  g_kb);
    cudaGetSymbolAddress((void**)&qb,   g_qb);
    cudaGetSymbolAddress((void**)&sbuf, g_scores);
    cudaGetSymbolAddress((void**)&wbuf, g_wts);
    cudaGetSymbolAddress((void**)&ibuf, g_idx);

    // 0) convert inputs to bf16
    {
        int X4 = NT * D_MODEL / 4;
        int total = X4 + (2 * D_KEY * D_MODEL) / 4 + 2 * (N_SUB * D_KEY) / 4;
        convert_kernel<<<(total + 255) / 256, 256>>>(
            (const float4*)x, (const float4*)Wq, (const float4*)keys_a, (const float4*)keys_b,
            (uint2*)xb, (uint2*)wqb, (uint2*)kbb, X4);
    }
    // 1) q = x @ Wq^T -> bf16 [NT,256]
    {
        dim3 grid(NT / 128, (2 * D_KEY) / 128, 1);
        hmma_gemm<true><<<grid, 256>>>(xb, D_MODEL, 0, wqb, wqb, D_MODEL,
                                       qb, 2 * D_KEY, 0, D_MODEL);
    }
    // 2) scores = q @ keys^T (both halves via grid.z) -> fp32 [NT,512]
    {
        dim3 grid(NT / 128, N_SUB / 128, 2);
        hmma_gemm<false><<<grid, 256>>>(qb, 2 * D_KEY, D_KEY,
                                        kbb, kbb + N_SUB * D_KEY, D_KEY,
                                        sbuf, 2 * N_SUB, N_SUB, D_KEY);
    }
    // 3) top-k + softmax
    topk_warp<<<(NT + 7) / 8, 256>>>(sbuf, wbuf, ibuf, NT);
    // 4) gather + gate + residual
    gather_kernel<<<NT, 256>>>(x, values, gate_w, gate_b, wbuf, ibuf, out);
}